// round 4
// baseline (speedup 1.0000x reference)
#include <cuda_runtime.h>
#include <cuda_bf16.h>

// DomainGate: T=8192 tokens, E=16 experts, capacity C = ceil(T/E) = 512.
// Outputs (flattened, float32): [ l_aux(1), combine1_sec(T*E*C), dispatch_mask(T*E*C) ]
// combine1_sec[t, e, c] = 1.0 iff e == domain_ids[t], token not padded, and
// c == (# prior active tokens with same expert) < capacity. dispatch_mask identical.
//
// Strategy: cudaMemsetAsync zero-fills the 536MB output (HBM-write-bound ~67us floor),
// then one tiny block computes the ordered per-expert cumsum and scatters ~14.7k ones.
//
// R2 fix: mask arrives as int32 (harness normalizes bool->int32), not bytes.
// Runtime-detect layout by scanning the first 8192 bytes: an int32 0/1 array has
// all bytes at (i%4!=0) equal to zero; a byte array has ~10% ones there.

#define NTOK 8192
#define NEXP 16
#define CAP  512
#define COMBINE_ELEMS (NTOK * NEXP * CAP)   // 67108864

#define NTHREADS 256
#define TOK_PER_THREAD (NTOK / NTHREADS)    // 32

__global__ __launch_bounds__(NTHREADS, 1)
void domain_gate_scatter(const int* __restrict__ domain_ids,
                         const void* __restrict__ mask_raw,
                         float* __restrict__ out) {
    // padded to 17 to avoid shared bank conflicts on column access
    __shared__ int cnt[NTHREADS][NEXP + 1];
    __shared__ int byte_mode;

    const int tid  = threadIdx.x;
    const int base = tid * TOK_PER_THREAD;

    // ---- Detect mask layout (bytes vs int32). Reads only first 8192 bytes: safe
    // in both layouts. int32 0/1 data has zero bytes at all i%4!=0 positions.
    if (tid == 0) byte_mode = 0;
    __syncthreads();
    {
        const unsigned char* mb = (const unsigned char*)mask_raw;
        int any = 0;
        for (int i = tid; i < NTOK; i += NTHREADS)
            if ((i & 3) && mb[i]) any = 1;
        if (any) byte_mode = 1;   // benign race: all writers store 1
    }
    __syncthreads();
    const int bm = byte_mode;

    // ---- Phase 1: per-thread local histogram of active tokens per expert
    int local[NEXP];
#pragma unroll
    for (int e = 0; e < NEXP; e++) local[e] = 0;

    int eid[TOK_PER_THREAD];
    unsigned char msk[TOK_PER_THREAD];   // 0 = active, nonzero = padded
    const unsigned char* mb = (const unsigned char*)mask_raw;
    const int*           mi = (const int*)mask_raw;
#pragma unroll 8
    for (int i = 0; i < TOK_PER_THREAD; i++) {
        eid[i] = domain_ids[base + i];
        msk[i] = bm ? mb[base + i] : (unsigned char)(mi[base + i] != 0);
    }
#pragma unroll 8
    for (int i = 0; i < TOK_PER_THREAD; i++) {
        if (!msk[i]) local[eid[i]]++;
    }
#pragma unroll
    for (int e = 0; e < NEXP; e++) cnt[tid][e] = local[e];
    __syncthreads();

    // ---- Phase 2: exclusive scan over the 256 chunks, one thread per expert.
    if (tid < NEXP) {
        int run = 0;
        for (int i = 0; i < NTHREADS; i++) {
            int v = cnt[i][tid];
            cnt[i][tid] = run;
            run += v;
        }
    }
    __syncthreads();

    // ---- Phase 3: replay tokens in order, assign capacity slots, scatter ones.
    int off[NEXP];
#pragma unroll
    for (int e = 0; e < NEXP; e++) off[e] = cnt[tid][e];

    float* __restrict__ combine = out + 1;
    float* __restrict__ dmask   = out + 1 + (long long)COMBINE_ELEMS;

#pragma unroll 8
    for (int i = 0; i < TOK_PER_THREAD; i++) {
        if (!msk[i]) {
            const int e   = eid[i];
            const int pos = off[e]++;
            if (pos < CAP) {   // capacity drop: token contributes nothing
                const long long idx =
                    (long long)(base + i) * (NEXP * CAP) + e * CAP + pos;
                combine[idx] = 1.0f;
                dmask[idx]   = 1.0f;
            }
        }
    }
}

extern "C" void kernel_launch(void* const* d_in, const int* in_sizes, int n_in,
                              void* d_out, int out_size) {
    // inputs per metadata order: [0] input float32 [8192,1024] (unused),
    // [1] domain_ids int32 [8192], [2] mask [8192] (int32 or bytes; detected on device)
    const int*  domain_ids = (const int*)d_in[1];
    const void* mask       = (const void*)d_in[2];
    float*      out        = (float*)d_out;

    // Zero the entire output (l_aux + all zero entries of combine/dispatch).
    cudaMemsetAsync(d_out, 0, (size_t)out_size * sizeof(float), 0);

    // Ordered cumsum + scatter (stream-ordered after the memset).
    domain_gate_scatter<<<1, NTHREADS>>>(domain_ids, mask, out);
}

// round 5
// speedup vs baseline: 1.0939x; 1.0939x over previous
#include <cuda_runtime.h>
#include <cuda_bf16.h>

// DomainGate: T=8192 tokens, E=16 experts, capacity C = ceil(T/E) = 512.
// Output (flattened float32): [ l_aux(1), combine1_sec(T*E*C), dispatch_mask(T*E*C) ]
// Row t of combine (8192 floats) is all-zero except combine[t, e, pos] = 1.0 where
// e = domain_ids[t], pos = # prior active same-expert tokens, if active and pos < C.
// dispatch_mask identical. l_aux = 0.
//
// R5: fuse zero-fill + ones into ONE full-chip store kernel (each CTA owns a row,
// writes zeros + its single one). Kills the 41us serial single-block scatter tail.
// A tiny scan kernel first computes slot[t] = e*C+pos (or -1) into device scratch.

#define NTOK 8192
#define NEXP 16
#define CAP  512
#define ROW  (NEXP * CAP)                    // 8192 floats per row
#define COMBINE_ELEMS (NTOK * ROW)           // 67108864

#define SCAN_THREADS 256
#define TOK_PER_THREAD (NTOK / SCAN_THREADS) // 32

__device__ int g_slot[NTOK];                 // e*CAP+pos, or -1 if no contribution

// ---------------------------------------------------------------------------
// K_scan: ordered per-expert cumsum -> g_slot. Single block (global sequential
// dependency), but only 8192 contiguous int stores — cheap.
// ---------------------------------------------------------------------------
__global__ __launch_bounds__(SCAN_THREADS, 1)
void domain_gate_scan(const int* __restrict__ domain_ids,
                      const void* __restrict__ mask_raw) {
    __shared__ int cnt[SCAN_THREADS][NEXP + 1];  // +1 pad vs bank conflicts
    __shared__ int byte_mode;

    const int tid  = threadIdx.x;
    const int base = tid * TOK_PER_THREAD;

    // Detect mask layout (bytes vs int32). int32 0/1 data has all-zero bytes at
    // positions i%4 != 0; reads stay within the first 8192 bytes (safe either way).
    if (tid == 0) byte_mode = 0;
    __syncthreads();
    {
        const unsigned char* mb = (const unsigned char*)mask_raw;
        int any = 0;
        for (int i = tid; i < NTOK; i += SCAN_THREADS)
            if ((i & 3) && mb[i]) any = 1;
        if (any) byte_mode = 1;  // benign race: all writers store 1
    }
    __syncthreads();
    const int bm = byte_mode;

    // Phase 1: per-thread histogram of active tokens per expert
    int local[NEXP];
#pragma unroll
    for (int e = 0; e < NEXP; e++) local[e] = 0;

    int eid[TOK_PER_THREAD];
    unsigned char msk[TOK_PER_THREAD];       // 0 = active
    const unsigned char* mb = (const unsigned char*)mask_raw;
    const int*           mi = (const int*)mask_raw;
#pragma unroll 8
    for (int i = 0; i < TOK_PER_THREAD; i++) {
        eid[i] = domain_ids[base + i];
        msk[i] = bm ? mb[base + i] : (unsigned char)(mi[base + i] != 0);
    }
#pragma unroll 8
    for (int i = 0; i < TOK_PER_THREAD; i++)
        if (!msk[i]) local[eid[i]]++;
#pragma unroll
    for (int e = 0; e < NEXP; e++) cnt[tid][e] = local[e];
    __syncthreads();

    // Phase 2: exclusive scan over the 256 chunks, one thread per expert
    if (tid < NEXP) {
        int run = 0;
        for (int i = 0; i < SCAN_THREADS; i++) {
            int v = cnt[i][tid];
            cnt[i][tid] = run;
            run += v;
        }
    }
    __syncthreads();

    // Phase 3: replay, emit slot index per token (contiguous stores)
    int off[NEXP];
#pragma unroll
    for (int e = 0; e < NEXP; e++) off[e] = cnt[tid][e];

#pragma unroll 8
    for (int i = 0; i < TOK_PER_THREAD; i++) {
        int s = -1;
        if (!msk[i]) {
            const int e   = eid[i];
            const int pos = off[e]++;
            if (pos < CAP) s = e * CAP + pos;   // capacity drop -> stays -1
        }
        g_slot[base + i] = s;
    }
}

// ---------------------------------------------------------------------------
// K_fill: one CTA per output row (16384 rows of 8192 floats = 32KB each).
// Rows 0..8191 = combine, rows 8192..16383 = dmask (same values). Zero-fill
// with float4 stores, then overwrite the single 1.0 (if any). Block 0 also
// writes l_aux = 0. This subsumes the memset at full HBM write bandwidth.
// ---------------------------------------------------------------------------
#define FILL_THREADS 256

__global__ __launch_bounds__(FILL_THREADS, 8)
void domain_gate_fill(float* __restrict__ out) {
    const int row = blockIdx.x;              // 0..16383
    const int t   = row & (NTOK - 1);
    const int tid = threadIdx.x;

    // Row base: combine row t at out+1+t*ROW; dmask row t at out+1+(8192+t)*ROW.
    float* __restrict__ p = out + 1 + (size_t)row * ROW;

    // Hoist the slot load (L2 broadcast across the 2 blocks sharing t)
    int s = -1;
    if (tid == 0) s = g_slot[t];

    if (row == 0 && tid == 0) out[0] = 0.0f;  // l_aux

    // p is 4 bytes past 16B alignment (out 256B-aligned, row stride 32KB).
    // Prologue: elements 0..2 scalar; then 2047 float4 from p+3; epilogue 8191.
    if (tid < 3) p[tid] = 0.0f;
    if (tid == 3) p[ROW - 1] = 0.0f;

    float4* __restrict__ v = (float4*)(p + 3);
    const float4 z = make_float4(0.f, 0.f, 0.f, 0.f);
#pragma unroll
    for (int k = 0; k < 8; k++) {
        const int idx = tid + k * FILL_THREADS;   // 0..2047
        if (idx < 2047) v[idx] = z;
    }
    __syncthreads();

    if (tid == 0 && s >= 0) p[s] = 1.0f;
}

extern "C" void kernel_launch(void* const* d_in, const int* in_sizes, int n_in,
                              void* d_out, int out_size) {
    // inputs: [0] input float32 [8192,1024] (unused),
    // [1] domain_ids int32 [8192], [2] mask [8192] (int32 or bytes; auto-detected)
    const int*  domain_ids = (const int*)d_in[1];
    const void* mask       = (const void*)d_in[2];
    float*      out        = (float*)d_out;

    domain_gate_scan<<<1, SCAN_THREADS>>>(domain_ids, mask);
    domain_gate_fill<<<2 * NTOK, FILL_THREADS>>>(out);
}

// round 7
// speedup vs baseline: 1.2270x; 1.1218x over previous
#include <cuda_runtime.h>
#include <cuda_bf16.h>

// DomainGate: T=8192 tokens, E=16 experts, capacity C = ceil(T/E) = 512.
// Output (flattened float32): [ l_aux(1), combine1_sec(T*E*C), dispatch_mask(T*E*C) ]
// Row t of combine (8192 floats) has a single 1.0 at e*C+pos (e = domain_ids[t],
// pos = # prior active same-expert tokens) iff token active and pos < C; else all 0.
// dispatch_mask identical. l_aux = 0.
//
// R6: (a) scan vectorized (int4 loads) + nibble-packed ids + bitmask -> no spills;
//     (b) fill fuses the 1.0 via compare-select (no syncthreads / overwrite);
//     (c) one CTA per token writes both rows with __stcs streaming stores.

#define NTOK 8192
#define NEXP 16
#define CAP  512
#define ROW  (NEXP * CAP)                    // 8192 floats per row
#define COMBINE_ELEMS (NTOK * ROW)           // 67108864

#define SCAN_THREADS 256
#define TOK_PER_THREAD (NTOK / SCAN_THREADS) // 32

__device__ int g_slot[NTOK];   // row-local slot e*CAP+pos, or -1

// ---------------------------------------------------------------------------
// K_scan: ordered per-expert cumsum -> g_slot. Single block.
// ---------------------------------------------------------------------------
__global__ __launch_bounds__(SCAN_THREADS, 1)
void domain_gate_scan(const int* __restrict__ domain_ids,
                      const void* __restrict__ mask_raw) {
    __shared__ int cnt[SCAN_THREADS][NEXP + 1];  // +1 pad vs bank conflicts
    __shared__ int byte_mode;

    const int tid  = threadIdx.x;
    const int base = tid * TOK_PER_THREAD;

    // Detect mask layout (bytes vs int32). int32 0/1 data has all-zero bytes at
    // positions i%4 != 0; reads stay inside the first 8192 bytes (safe either way).
    if (tid == 0) byte_mode = 0;
    __syncthreads();
    {
        const uint4* m16 = (const uint4*)mask_raw;   // first 512 uint4 = 8192 bytes
        uint4 w = m16[tid + ((tid & 1) ? 256 : 0) - ((tid & 1) ? 1 : 0)]; // tid or tid+255? keep simple:
        // (re-read straightforwardly below; above line avoided — see loop)
        int any = 0;
        for (int i = tid; i < 512; i += SCAN_THREADS) {
            uint4 q = m16[i];
            if ((q.x | q.y | q.z | q.w) & 0xFFFFFF00u) any = 1;
        }
        (void)w;
        if (any) byte_mode = 1;   // benign race: all writers store 1
    }
    __syncthreads();
    const int bm = byte_mode;

    // ---- Phase 1: vector loads; pack 32 expert ids into 4 nibble words and the
    // 32 pad bits into one word. Histogram active tokens per expert.
    unsigned int pk[4] = {0u, 0u, 0u, 0u};
    unsigned int pad   = 0u;

    if (!bm) {
        const int4* ids4 = (const int4*)domain_ids;
        const int4* m4   = (const int4*)mask_raw;
#pragma unroll
        for (int k = 0; k < 8; k++) {          // 4 tokens per iter
            int4 a = ids4[tid * 8 + k];
            int4 m = m4[tid * 8 + k];
            const int i0 = k * 4;
            pk[i0 >> 3] |= (unsigned)(a.x & 15) << (((i0 + 0) & 7) * 4);
            pk[i0 >> 3] |= (unsigned)(a.y & 15) << (((i0 + 1) & 7) * 4);
            pk[i0 >> 3] |= (unsigned)(a.z & 15) << (((i0 + 2) & 7) * 4);
            pk[i0 >> 3] |= (unsigned)(a.w & 15) << (((i0 + 3) & 7) * 4);
            if (m.x) pad |= 1u << (i0 + 0);
            if (m.y) pad |= 1u << (i0 + 1);
            if (m.z) pad |= 1u << (i0 + 2);
            if (m.w) pad |= 1u << (i0 + 3);
        }
    } else {
        const unsigned char* mb = (const unsigned char*)mask_raw;
        const int4* ids4 = (const int4*)domain_ids;
#pragma unroll
        for (int k = 0; k < 8; k++) {
            int4 a = ids4[tid * 8 + k];
            const int i0 = k * 4;
            pk[i0 >> 3] |= (unsigned)(a.x & 15) << (((i0 + 0) & 7) * 4);
            pk[i0 >> 3] |= (unsigned)(a.y & 15) << (((i0 + 1) & 7) * 4);
            pk[i0 >> 3] |= (unsigned)(a.z & 15) << (((i0 + 2) & 7) * 4);
            pk[i0 >> 3] |= (unsigned)(a.w & 15) << (((i0 + 3) & 7) * 4);
            if (mb[base + i0 + 0]) pad |= 1u << (i0 + 0);
            if (mb[base + i0 + 1]) pad |= 1u << (i0 + 1);
            if (mb[base + i0 + 2]) pad |= 1u << (i0 + 2);
            if (mb[base + i0 + 3]) pad |= 1u << (i0 + 3);
        }
    }

    int local[NEXP];
#pragma unroll
    for (int e = 0; e < NEXP; e++) local[e] = 0;
#pragma unroll
    for (int i = 0; i < TOK_PER_THREAD; i++) {
        const int e = (pk[i >> 3] >> ((i & 7) * 4)) & 15;
        if (!((pad >> i) & 1u)) local[e]++;
    }
#pragma unroll
    for (int e = 0; e < NEXP; e++) cnt[tid][e] = local[e];
    __syncthreads();

    // ---- Phase 2: exclusive scan over 256 chunks, one thread per expert
    if (tid < NEXP) {
        int run = 0;
        for (int i = 0; i < SCAN_THREADS; i++) {
            int v = cnt[i][tid];
            cnt[i][tid] = run;
            run += v;
        }
    }
    __syncthreads();

    // ---- Phase 3: replay packed tokens in order, emit slots (contiguous stores)
    int off[NEXP];
#pragma unroll
    for (int e = 0; e < NEXP; e++) off[e] = cnt[tid][e];

#pragma unroll
    for (int i = 0; i < TOK_PER_THREAD; i++) {
        int s = -1;
        if (!((pad >> i) & 1u)) {
            const int e   = (pk[i >> 3] >> ((i & 7) * 4)) & 15;
            const int pos = off[e]++;
            if (pos < CAP) s = e * CAP + pos;   // capacity drop -> -1
        }
        g_slot[base + i] = s;
    }
}

// ---------------------------------------------------------------------------
// K_fill: one CTA per token t. Writes combine row t AND dmask row t (64KB),
// with the single 1.0 fused into the store values via compare-select.
// Streaming (evict-first) stores: pure write-once data, no reuse to protect.
// ---------------------------------------------------------------------------
#define FILL_THREADS 256

__global__ __launch_bounds__(FILL_THREADS, 8)
void domain_gate_fill(float* __restrict__ out) {
    const int t   = blockIdx.x;
    const int tid = threadIdx.x;

    const int s = g_slot[t];   // L1/L2 broadcast across the block

    float* __restrict__ pc = out + 1 + (size_t)t * ROW;                  // combine row
    float* __restrict__ pd = pc + (size_t)COMBINE_ELEMS;                 // dmask row

    if (t == 0 && tid == 0) out[0] = 0.0f;   // l_aux

    // Rows start 4B past 16B alignment: scalar head (0..2) and tail (8191),
    // float4 body over [3, 8191) = 2047 vectors.
    if (tid < 3) {
        const float v = (tid == s) ? 1.0f : 0.0f;
        __stcs(pc + tid, v);
        __stcs(pd + tid, v);
    }
    if (tid == 3) {
        const float v = (s == ROW - 1) ? 1.0f : 0.0f;
        __stcs(pc + ROW - 1, v);
        __stcs(pd + ROW - 1, v);
    }

    float4* __restrict__ vc = (float4*)(pc + 3);
    float4* __restrict__ vd = (float4*)(pd + 3);
#pragma unroll
    for (int k = 0; k < 8; k++) {
        const int idx = tid + k * FILL_THREADS;   // 0..2047
        if (idx < 2047) {
            const int e0 = 3 + idx * 4;           // row-local element of .x
            float4 v;
            v.x = (e0 + 0 == s) ? 1.0f : 0.0f;
            v.y = (e0 + 1 == s) ? 1.0f : 0.0f;
            v.z = (e0 + 2 == s) ? 1.0f : 0.0f;
            v.w = (e0 + 3 == s) ? 1.0f : 0.0f;
            __stcs(vc + idx, v);
            __stcs(vd + idx, v);
        }
    }
}

extern "C" void kernel_launch(void* const* d_in, const int* in_sizes, int n_in,
                              void* d_out, int out_size) {
    // inputs: [0] input float32 [8192,1024] (unused),
    // [1] domain_ids int32 [8192], [2] mask [8192] (int32 or bytes; auto-detected)
    const int*  domain_ids = (const int*)d_in[1];
    const void* mask       = (const void*)d_in[2];
    float*      out        = (float*)d_out;

    domain_gate_scan<<<1, SCAN_THREADS>>>(domain_ids, mask);
    domain_gate_fill<<<NTOK, FILL_THREADS>>>(out);
}

// round 8
// speedup vs baseline: 1.2649x; 1.0309x over previous
#include <cuda_runtime.h>
#include <cuda_bf16.h>

// DomainGate: T=8192 tokens, E=16 experts, capacity C = ceil(T/E) = 512.
// Output (flattened float32): [ l_aux(1), combine1_sec(T*E*C), dispatch_mask(T*E*C) ]
// combine[t, e, pos] = 1.0 where e = domain_ids[t], pos = # prior active
// same-expert tokens, iff token active (mask=0) and pos < C; all else 0.
// dispatch_mask identical. l_aux = 0.
//
// R7: (a) zero-fill via cudaMemsetAsync (measured fastest, ~7.5 TB/s);
//     (b) ones via wide 8192-thread scatter kernel (~3us, vs 41us single-block R4);
//     (c) scan phase-2 parallelized: one warp per expert, shuffle-scan segments.

#define NTOK 8192
#define NEXP 16
#define CAP  512
#define ROW  (NEXP * CAP)                    // 8192
#define COMBINE_ELEMS (NTOK * ROW)           // 67108864

#define SCAN_THREADS 512                     // 16 warps = 16 experts
#define TPT (NTOK / SCAN_THREADS)            // 16 tokens per thread

__device__ int g_slot[NTOK];                 // e*CAP+pos, or -1

// ---------------------------------------------------------------------------
// K_scan: ordered per-expert cumsum -> g_slot. Single block, 512 threads.
// ---------------------------------------------------------------------------
__global__ __launch_bounds__(SCAN_THREADS, 1)
void domain_gate_scan(const int* __restrict__ domain_ids,
                      const void* __restrict__ mask_raw) {
    __shared__ int cnt[SCAN_THREADS][NEXP + 1];   // +1 pad vs bank conflicts
    __shared__ int byte_mode;

    const int tid  = threadIdx.x;
    const int warp = tid >> 5;
    const int lane = tid & 31;
    const int base = tid * TPT;

    // ---- Mask layout detect (int32 vs bytes): one uint4 per thread covers the
    // first 8192 bytes exactly; int32 0/1 data has zero upper bytes everywhere.
    if (tid == 0) byte_mode = 0;
    __syncthreads();
    {
        const uint4 q = ((const uint4*)mask_raw)[tid];
        if ((q.x | q.y | q.z | q.w) & 0xFFFFFF00u) byte_mode = 1;
    }
    __syncthreads();
    const int bm = byte_mode;

    // ---- Phase 1: vector loads; pack 16 ids into 2 nibble words + 16 pad bits.
    unsigned int pk[2] = {0u, 0u};
    unsigned int pad   = 0u;
    const int4* ids4 = (const int4*)domain_ids;

    if (!bm) {
        const int4* m4 = (const int4*)mask_raw;
#pragma unroll
        for (int k = 0; k < 4; k++) {
            const int4 a = ids4[tid * 4 + k];
            const int4 m = m4[tid * 4 + k];
            const int i0 = k * 4;
            pk[i0 >> 3] |= (unsigned)(a.x & 15) << (((i0 + 0) & 7) * 4);
            pk[i0 >> 3] |= (unsigned)(a.y & 15) << (((i0 + 1) & 7) * 4);
            pk[i0 >> 3] |= (unsigned)(a.z & 15) << (((i0 + 2) & 7) * 4);
            pk[i0 >> 3] |= (unsigned)(a.w & 15) << (((i0 + 3) & 7) * 4);
            if (m.x) pad |= 1u << (i0 + 0);
            if (m.y) pad |= 1u << (i0 + 1);
            if (m.z) pad |= 1u << (i0 + 2);
            if (m.w) pad |= 1u << (i0 + 3);
        }
    } else {
        const unsigned char* mb = (const unsigned char*)mask_raw;
#pragma unroll
        for (int k = 0; k < 4; k++) {
            const int4 a = ids4[tid * 4 + k];
            const int i0 = k * 4;
            pk[i0 >> 3] |= (unsigned)(a.x & 15) << (((i0 + 0) & 7) * 4);
            pk[i0 >> 3] |= (unsigned)(a.y & 15) << (((i0 + 1) & 7) * 4);
            pk[i0 >> 3] |= (unsigned)(a.z & 15) << (((i0 + 2) & 7) * 4);
            pk[i0 >> 3] |= (unsigned)(a.w & 15) << (((i0 + 3) & 7) * 4);
            if (mb[base + i0 + 0]) pad |= 1u << (i0 + 0);
            if (mb[base + i0 + 1]) pad |= 1u << (i0 + 1);
            if (mb[base + i0 + 2]) pad |= 1u << (i0 + 2);
            if (mb[base + i0 + 3]) pad |= 1u << (i0 + 3);
        }
    }

    int local[NEXP];
#pragma unroll
    for (int e = 0; e < NEXP; e++) local[e] = 0;
#pragma unroll
    for (int i = 0; i < TPT; i++) {
        const int e = (pk[i >> 3] >> ((i & 7) * 4)) & 15;
        if (!((pad >> i) & 1u)) local[e]++;
    }
#pragma unroll
    for (int e = 0; e < NEXP; e++) cnt[tid][e] = local[e];
    __syncthreads();

    // ---- Phase 2: warp w scans expert w over 512 chunk counts.
    // 16 segments of 32: shuffle inclusive scan + running carry.
    {
        const int e = warp;                    // 16 warps, 16 experts
        int carry = 0;
#pragma unroll
        for (int seg = 0; seg < 16; seg++) {
            const int i = seg * 32 + lane;
            const int v = cnt[i][e];
            int x = v;
#pragma unroll
            for (int d = 1; d < 32; d <<= 1) {
                const int y = __shfl_up_sync(0xFFFFFFFFu, x, d);
                if (lane >= d) x += y;
            }
            cnt[i][e] = carry + x - v;         // exclusive
            carry += __shfl_sync(0xFFFFFFFFu, x, 31);
        }
    }
    __syncthreads();

    // ---- Phase 3: replay, emit slot per token (int4 stores)
    int off[NEXP];
#pragma unroll
    for (int e = 0; e < NEXP; e++) off[e] = cnt[tid][e];

    int4* gs4 = (int4*)g_slot;
#pragma unroll
    for (int k = 0; k < 4; k++) {
        int4 sv;
        int* sp = (int*)&sv;
#pragma unroll
        for (int j = 0; j < 4; j++) {
            const int i = k * 4 + j;
            int s = -1;
            if (!((pad >> i) & 1u)) {
                const int e   = (pk[i >> 3] >> ((i & 7) * 4)) & 15;
                const int pos = off[e]++;
                if (pos < CAP) s = e * CAP + pos;
            }
            sp[j] = s;
        }
        gs4[tid * 4 + k] = sv;
    }
}

// ---------------------------------------------------------------------------
// K_ones: one thread per token; scattered 1.0 stores into both tensors.
// ---------------------------------------------------------------------------
__global__ __launch_bounds__(256)
void domain_gate_ones(float* __restrict__ out) {
    const int t = blockIdx.x * 256 + threadIdx.x;   // 0..8191
    const int s = g_slot[t];
    if (s >= 0) {
        const size_t idx = 1 + (size_t)t * ROW + s;
        out[idx]                          = 1.0f;   // combine1_sec
        out[idx + (size_t)COMBINE_ELEMS]  = 1.0f;   // dispatch_mask
    }
}

extern "C" void kernel_launch(void* const* d_in, const int* in_sizes, int n_in,
                              void* d_out, int out_size) {
    // inputs: [0] input float32 [8192,1024] (unused),
    // [1] domain_ids int32 [8192], [2] mask [8192] (int32 or bytes; auto-detected)
    const int*  domain_ids = (const int*)d_in[1];
    const void* mask       = (const void*)d_in[2];
    float*      out        = (float*)d_out;

    // Zero everything (l_aux + both tensors) at peak memset bandwidth.
    cudaMemsetAsync(d_out, 0, (size_t)out_size * sizeof(float), 0);
    // Ordered per-expert cumsum -> g_slot (independent of memset; serialized anyway).
    domain_gate_scan<<<1, SCAN_THREADS>>>(domain_ids, mask);
    // Scatter the ~14.7k ones over both tensors, fully parallel.
    domain_gate_ones<<<NTOK / 256, 256>>>(out);
}